// round 17
// baseline (speedup 1.0000x reference)
#include <cuda_runtime.h>
#include <cstdint>

// ---------------- problem constants ----------------
#define NNZ      220939
#define CIN      32
#define COUT     64
#define KVOL     27
#define OUT_X    11
#define OUT_Y    400
#define OUT_Z    352
#define N_ROWS   (OUT_X * OUT_Y * OUT_Z)      // 1,548,800 output rows
#define BM_WORDS (N_ROWS / 32)                // 48,400 bitmap words

// ---------------- device scratch (static, allocation-free) ----------------
__device__ int2     g_rules[(size_t)KVOL * NNZ];   // 47.7 MB rulebook
__device__ int      g_cnt[KVOL * 128];             // counters, 512B apart
__device__ unsigned g_bm[BM_WORDS];                // active-row bitmap, 194KB
__device__ int      g_done;                        // completion ctr

#define ZERO_ROW(p) \
    asm volatile("st.global.v8.f32 [%0], {%1,%1,%1,%1,%1,%1,%1,%1};" \
                 :: "l"(p), "f"(0.f) : "memory")

// ---------------- kernel A: build rules + zero ACTIVE rows + bitmap ----------
// For every valid (point, offset) pair: append to rulebook, mark the output
// row in the bitmap, and zero that row directly (duplicate zero stores are
// idempotent; L2 absorbs dups). This removes the dense 396MB zero from the
// serial critical path: only ~154MB of active rows is zeroed here.
#define BUILD_BLOCKS 864   // ceil(NNZ/256)

__global__ void build_rules(const int* __restrict__ coords,
                            float* __restrict__ out) {
    int i    = blockIdx.x * blockDim.x + threadIdx.x;
    int lane = threadIdx.x & 31;
    bool active = (i < NNZ);

    int cx = 0, cy = 0, cz = 0;
    if (active) {
        cx = coords[i * 3 + 0];
        cy = coords[i * 3 + 1];
        cz = coords[i * 3 + 2];
    }

    bool vX[3], vY[3], vZ[3];
    int  qX[3], qY[3], qZ[3];
#pragma unroll
    for (int o = 0; o < 3; o++) {
        int ox = cx + 1 - o; vX[o] = (ox >= 0) && !(ox & 1) && ((ox >> 1) < OUT_X); qX[o] = ox >> 1;
        int oy = cy + 1 - o; vY[o] = (oy >= 0) && !(oy & 1) && ((oy >> 1) < OUT_Y); qY[o] = oy >> 1;
        int oz = cz + 1 - o; vZ[o] = (oz >= 0) && !(oz & 1) && ((oz >> 1) < OUT_Z); qZ[o] = oz >> 1;
    }

#pragma unroll
    for (int kx = 0; kx < 3; kx++) {
#pragma unroll
        for (int ky = 0; ky < 3; ky++) {
#pragma unroll
            for (int kz = 0; kz < 3; kz++) {
                int k = (kx * 3 + ky) * 3 + kz;
                bool valid = active && vX[kx] && vY[ky] && vZ[kz];
                int flat = 0;
                if (valid) flat = (qX[kx] * OUT_Y + qY[ky]) * OUT_Z + qZ[kz];

                unsigned mask = __ballot_sync(0xffffffffu, valid);
                if (mask) {
                    int leader = __ffs(mask) - 1;
                    int base = 0;
                    if (lane == leader)
                        base = atomicAdd(&g_cnt[k * 128], __popc(mask));
                    base = __shfl_sync(0xffffffffu, base, leader);
                    if (valid) {
                        int pos = base + __popc(mask & ((1u << lane) - 1u));
                        g_rules[(size_t)k * NNZ + pos] = make_int2(i, flat);
                        atomicOr(&g_bm[flat >> 5], 1u << (flat & 31));
                        float* p = out + (size_t)flat * COUT;
#pragma unroll
                        for (int q = 0; q < 8; q++) ZERO_ROW(p + q * 8);
                    }
                }
            }
        }
    }
}

// ---------------- kernel B: GEMM (y>=1) + zero-inactive rows (y==0) ----------
// y==0 blocks zero every bitmap-clear row (disjoint from all scatter targets,
// so they overlap the GEMM freely) and reset the bitmap for the next replay.
// y>=1: R14 GEMM (tf32 MMA, B-in-padded-smem, 2-deep cp.async, red.v4
// scatter) with k = y-1. Epilogue resets counters after ALL blocks finish.
#define TILE_P  64
#define GEMM_GX 64
#define WSTRIDE 72

#define MMA_TF32(c0,c1,c2,c3, a0,a1,a2,a3, b0,b1) \
    asm("mma.sync.aligned.m16n8k8.row.col.f32.tf32.tf32.f32 " \
        "{%0,%1,%2,%3}, {%4,%5,%6,%7}, {%8,%9}, {%0,%1,%2,%3};" \
        : "+f"(c0), "+f"(c1), "+f"(c2), "+f"(c3) \
        : "r"(a0), "r"(a1), "r"(a2), "r"(a3), "r"(b0), "r"(b1))

__device__ __forceinline__ unsigned f2tf32(float f) {
    unsigned u;
    asm("cvt.rna.tf32.f32 %0, %1;" : "=r"(u) : "f"(f));
    return u;
}

__device__ __forceinline__ void cp16(unsigned smem, const void* gmem) {
    asm volatile("cp.async.ca.shared.global [%0], [%1], 16;"
                 :: "r"(smem), "l"(gmem));
}
#define CP_COMMIT() asm volatile("cp.async.commit_group;")
#define CP_WAIT0()  asm volatile("cp.async.wait_group 0;")
#define CP_WAIT1()  asm volatile("cp.async.wait_group 1;")

__global__ __launch_bounds__(256, 4)
void gather_gemm_scatter(const float* __restrict__ features,
                         const float* __restrict__ weight,
                         float* __restrict__ out) {
    const int tid  = threadIdx.x;

    __shared__ unsigned swt[CIN * WSTRIDE];       // tf32 weights, padded
    __shared__ float    sfu[3][TILE_P * 36];      // fp32 features, 3 buffers
    __shared__ int      sflat[3][TILE_P];

    if (blockIdx.y == 0) {
        // ---- zero INACTIVE rows + reset bitmap -----------------------------
        int tidg = blockIdx.x * 256 + tid;
        for (int wd = tidg; wd < BM_WORDS; wd += GEMM_GX * 256) {
            unsigned bits = g_bm[wd];
            int rbase = wd * 32;
            if (bits != 0xffffffffu) {
#pragma unroll 4
                for (int b = 0; b < 32; b++) {
                    if (!(bits & (1u << b))) {
                        float* p = out + (size_t)(rbase + b) * COUT;
#pragma unroll
                        for (int q = 0; q < 8; q++) ZERO_ROW(p + q * 8);
                    }
                }
            }
            g_bm[wd] = 0;                         // replay reset (free)
        }
    } else {
        const int k   = blockIdx.y - 1;
        const int cnt = g_cnt[k * 128];

        const int w    = tid >> 5;
        const int lane = tid & 31;
        const int g    = lane >> 2;      // group id: A rows / B cols
        const int t    = lane & 3;       // thread-in-group: A cols / B rows
        const int slab = w & 3;
        const int half = w >> 2;

        int nt = 0;
        {
            int tiles = (cnt + TILE_P - 1) / TILE_P;
            if ((int)blockIdx.x < tiles)
                nt = (tiles - blockIdx.x + GEMM_GX - 1) / GEMM_GX;
        }

        if (nt > 0) {
            // ---- stage W[k] into padded shared, convert to tf32 ------------
            {
                const float4* wk4 = (const float4*)(weight + (size_t)k * (CIN * COUT));
#pragma unroll
                for (int e = tid; e < CIN * COUT / 4; e += 256) {
                    float4 v = wk4[e];
                    int k0 = e >> 4;
                    int n4 = e & 15;
                    unsigned* d = &swt[k0 * WSTRIDE + n4 * 4];
                    d[0] = f2tf32(v.x);
                    d[1] = f2tf32(v.y);
                    d[2] = f2tf32(v.z);
                    d[3] = f2tf32(v.w);
                }
            }

            const int2* rules_k = g_rules + (size_t)k * NNZ;
            const int p0 = tid >> 3;
            const int p1 = 32 + (tid >> 3);
            const int c4 = tid & 7;

            auto load_rules = [&](int i, int2& ra, int2& rb) {
                int base = (blockIdx.x + i * GEMM_GX) * TILE_P;
                int ja = base + p0; if (ja >= cnt) ja = cnt - 1;
                int jb = base + p1; if (jb >= cnt) jb = cnt - 1;
                ra = __ldg(&rules_k[ja]);
                rb = __ldg(&rules_k[jb]);
            };
            auto issue_feat = [&](int buf, int2 ra, int2 rb) {
                unsigned sb = (unsigned)__cvta_generic_to_shared(&sfu[buf][0]);
                cp16(sb + (p0 * 36 + c4 * 4) * 4,
                     features + (size_t)ra.x * CIN + c4 * 4);
                cp16(sb + (p1 * 36 + c4 * 4) * 4,
                     features + (size_t)rb.x * CIN + c4 * 4);
                if (c4 == 0) { sflat[buf][p0] = ra.y; sflat[buf][p1] = rb.y; }
            };

            int issued = (nt < 2) ? nt : 2;
            for (int i = 0; i < issued; i++) {
                int2 ra, rb;
                load_rules(i, ra, rb);
                issue_feat(i, ra, rb);
                CP_COMMIT();
            }
            __syncthreads();

            const int r0 = slab * 16 + g;
            const int bcol = half * 32 + g;

            int buf = 0;
            for (int i = 0; i < nt; i++) {
                const bool has2 = (i + 2 < nt);
                int2 ra, rb;
                if (has2) load_rules(i + 2, ra, rb);

                if (issued - i - 1 >= 1) CP_WAIT1(); else CP_WAIT0();
                __syncthreads();

                float C0[4], C1[4], C2[4], C3[4];
#pragma unroll
                for (int j = 0; j < 4; j++) { C0[j] = C1[j] = C2[j] = C3[j] = 0.f; }

                const float* fb = sfu[buf];
#pragma unroll
                for (int kk = 0; kk < 4; kk++) {
                    int cbase = kk * 8 + t;
                    unsigned a0 = f2tf32(fb[r0 * 36 + cbase]);
                    unsigned a1 = f2tf32(fb[(r0 + 8) * 36 + cbase]);
                    unsigned a2 = f2tf32(fb[r0 * 36 + cbase + 4]);
                    unsigned a3 = f2tf32(fb[(r0 + 8) * 36 + cbase + 4]);
                    const unsigned* b0p = &swt[(kk * 8 + t) * WSTRIDE + bcol];
                    const unsigned* b1p = &swt[(kk * 8 + t + 4) * WSTRIDE + bcol];
#pragma unroll
                    for (int j = 0; j < 4; j++) {
                        unsigned b0 = b0p[j * 8];
                        unsigned b1 = b1p[j * 8];
                        MMA_TF32(C0[j], C1[j], C2[j], C3[j],
                                 a0, a1, a2, a3, b0, b1);
                    }
                }

                const int  base = (blockIdx.x + i * GEMM_GX) * TILE_P;
                const bool v0 = (base + r0)     < cnt;
                const bool v1 = (base + r0 + 8) < cnt;
                const int  f0 = sflat[buf][r0];
                const int  f1 = sflat[buf][r0 + 8];
                const int  colbase = half * 32 + 2 * t;
#pragma unroll
                for (int j = 0; j < 4; j++) {
                    float x0 = __shfl_down_sync(0xffffffffu, C0[j], 1);
                    float x1 = __shfl_down_sync(0xffffffffu, C1[j], 1);
                    float x2 = __shfl_down_sync(0xffffffffu, C2[j], 1);
                    float x3 = __shfl_down_sync(0xffffffffu, C3[j], 1);
                    if ((t & 1) == 0) {
                        if (v0) {
                            const float* dst = out + (size_t)f0 * COUT + colbase + j * 8;
                            asm volatile(
                                "{ .reg .u64 pg; cvta.to.global.u64 pg, %0;\n\t"
                                "  red.global.add.v4.f32 [pg], {%1, %2, %3, %4}; }"
                                :: "l"(dst), "f"(C0[j]), "f"(C1[j]), "f"(x0), "f"(x1)
                                : "memory");
                        }
                        if (v1) {
                            const float* dst = out + (size_t)f1 * COUT + colbase + j * 8;
                            asm volatile(
                                "{ .reg .u64 pg; cvta.to.global.u64 pg, %0;\n\t"
                                "  red.global.add.v4.f32 [pg], {%1, %2, %3, %4}; }"
                                :: "l"(dst), "f"(C2[j]), "f"(C3[j]), "f"(x2), "f"(x3)
                                : "memory");
                        }
                    }
                }

                if (has2) {
                    int nbuf = buf + 2; if (nbuf >= 3) nbuf -= 3;
                    issue_feat(nbuf, ra, rb);
                    CP_COMMIT();
                    issued++;
                }
                if (++buf == 3) buf = 0;
            }
        }
    }

    // ---- epilogue: last finished block resets counters for next replay -----
    __syncthreads();
    if (tid == 0) {
        int d = atomicAdd(&g_done, 1);
        if (d == GEMM_GX * (KVOL + 1) - 1) {
#pragma unroll
            for (int i = 0; i < KVOL; i++) g_cnt[i * 128] = 0;
            g_done = 0;
        }
    }
}

// ---------------- launch ----------------
extern "C" void kernel_launch(void* const* d_in, const int* in_sizes, int n_in,
                              void* d_out, int out_size) {
    const float* features = (const float*)d_in[0];
    const int*   coords   = (const int*)d_in[1];
    const float* weight   = (const float*)d_in[2];
    float*       out      = (float*)d_out;

    build_rules<<<BUILD_BLOCKS, 256>>>(coords, out);

    dim3 grid(GEMM_GX, KVOL + 1);
    gather_gemm_scatter<<<grid, 256>>>(features, weight, out);
}